// round 9
// baseline (speedup 1.0000x reference)
#include <cuda_runtime.h>

#define NT    512
#define PG    8                  // points per group (= n_steps-2 here)
#define DD    64
#define HH    2048
#define CCH   256
#define CCHP  260                // activation stride: 260 % 32 = 4 -> 8 p-slices conflict-free
#define LD    260                // padded W1s row stride (floats), 260 % 32 = 4
#define LD4   65                 // in float4
#define NCHK  8
#define MAXB  64

__device__ float g_wpart[MAXB * NCHK * DD * PG];
__device__ float g_cpart[MAXB * NCHK * DD * PG];
__device__ unsigned g_cntA[MAXB];
__device__ unsigned g_cntB[MAXB];

__device__ __forceinline__ float tanh_fast(float x)
{
    float y;
    asm("tanh.approx.f32 %0, %1;" : "=f"(y) : "f"(x));
    return y;
}

__device__ __forceinline__ void load_chunk_async(float* buf, const float* __restrict__ W1,
                                                 int j0, int tid)
{
    #pragma unroll
    for (int s = 0; s < 8; ++s) {
        int g = s * NT + tid;            // 4096 16B segments
        int d = g >> 6;
        int k = g & 63;
        const float* src = W1 + d * HH + j0 + k * 4;
        unsigned dst = (unsigned)__cvta_generic_to_shared(buf + d * LD + k * 4);
        asm volatile("cp.async.cg.shared.global [%0], [%1], 16;" :: "r"(dst), "l"(src));
    }
    asm volatile("cp.async.commit_group;");
}

// row pass: one output per thread. row = warp*4 + lane>>3, p = lane&7.
// W reads: 4 distinct rows/warp (8-lane broadcast). Act reads: 8 distinct
// p-slices at banks 4p..4p+3 -> conflict-free.
__device__ __forceinline__ void row_pass(const float* __restrict__ W1s,
                                         const float* __restrict__ src_p,   // [p][CCHP]
                                         float* __restrict__ dstg,          // [DD*PG]
                                         int lane, int warp)
{
    int row = warp * 4 + (lane >> 3);
    int p = lane & 7;
    const float4* W4 = (const float4*)W1s;
    const float4* aP = (const float4*)(src_p + p * CCHP);
    float a0 = 0.f, a1 = 0.f;
    #pragma unroll 8
    for (int j4 = 0; j4 < CCH / 4; j4 += 2) {
        float4 w0 = W4[row * LD4 + j4];
        float4 w1 = W4[row * LD4 + j4 + 1];
        float4 b0 = aP[j4], b1 = aP[j4 + 1];
        a0 += w0.x * b0.x + w0.y * b0.y + w0.z * b0.z + w0.w * b0.w;
        a1 += w1.x * b1.x + w1.y * b1.y + w1.z * b1.z + w1.w * b1.w;
    }
    dstg[row * PG + p] = a0 + a1;
}

__global__ __launch_bounds__(NT, 2) void geo_one(
    const float* __restrict__ x0, const float* __restrict__ xT,
    const float* __restrict__ W1, const float* __restrict__ b1,
    const float* __restrict__ W2, float* __restrict__ out,
    int B, int O, int n_steps, int nInterior)
{
    extern __shared__ float sm[];
    float* W1s   = sm;                   // DD*LD = 16640
    float* a_sh  = W1s + DD * LD;        // 256
    float* asp_p = a_sh + CCH;           // [p][CCHP] : 2080
    float* as_p  = asp_p + PG * CCHP;    // [p][CCHP] : 2080
    float* ue    = as_p + PG * CCHP;     // [2][CCH]  : 512 (u then e)
    float* wp    = ue + 2 * CCH;         // [d][p] : 512
    float* csh   = wp + DD * PG;         // [p][d] : 512
    float* x0g   = csh + PG * DD;        // 64
    float* dlt   = x0g + DD;             // 64
    float* red   = dlt + DD;             // 16
    __shared__ int slast;

    int tid = threadIdx.x, lane = tid & 31, warp = tid >> 5;
    int g = blockIdx.x;                  // batch index
    int c = blockIdx.y;                  // W1 chunk
    int j0 = c * CCH;
    int nsPerB = n_steps - 2;            // <= PG
    float invn1 = 1.0f / (float)(n_steps - 1);

    load_chunk_async(W1s, W1, j0, tid);

    // ---------- prep ----------
    if (tid < DD) {
        float a0 = x0[g * DD + tid];
        float aT = xT[g * DD + tid];
        x0g[tid] = a0;
        dlt[tid] = aT - a0;
        if (c == 0) {
            out[g * DD + tid] = a0;
            out[((n_steps - 1) * B + g) * DD + tid] = aT;
        }
    }
    __syncthreads();
    if (warp == 0) {
        float s = dlt[lane] * dlt[lane] + dlt[lane + 32] * dlt[lane + 32];
        #pragma unroll
        for (int o = 16; o; o >>= 1) s += __shfl_xor_sync(0xffffffffu, s, o);
        if (lane == 0) red[0] = 1.0f / sqrtf(s);
    }
    __syncthreads();

    // a_j = inv * (W2[j,:] . dlt)   for the 256 j of this chunk
    if (tid < CCH) {
        float inv = red[0];
        const float4* w2r = (const float4*)(W2 + (size_t)(j0 + tid) * O);
        const float4* v4  = (const float4*)dlt;
        float acc = 0.f;
        #pragma unroll
        for (int k = 0; k < DD / 4; ++k) {
            float4 w = w2r[k], vv = v4[k];
            acc += w.x * vv.x + w.y * vv.y + w.z * vv.z + w.w * vv.w;
        }
        a_sh[tid] = acc * inv;
    }
    asm volatile("cp.async.wait_group 0;");
    __syncthreads();

    int j  = tid & (CCH - 1);
    int ph = tid >> 8;                   // 0 or 1

    // ---------- phase A column: u_j (ph=0) / e_j (ph=1) ----------
    {
        const float* src = ph ? dlt : x0g;
        float acc = ph ? 0.f : b1[j0 + j];
        #pragma unroll 8
        for (int d = 0; d < DD; ++d)
            acc += src[d] * W1s[d * LD + j];
        ue[ph * CCH + j] = acc;
    }
    __syncthreads();

    // as/asp for this thread's 4 points
    {
        float u = ue[j], e = ue[CCH + j];
        float a = a_sh[j];
        #pragma unroll
        for (int k = 0; k < 4; ++k) {
            int p = ph * 4 + k;
            int pc = (p < nsPerB) ? p : (nsPerB - 1);
            float tpar = (float)(pc + 1) * invn1;
            float t = tanh_fast(u + tpar * e);
            float sf = 1.0f - t * t;
            as_p[p * CCHP + j]  = a * sf;
            asp_p[p * CCHP + j] = a * (-2.0f * t * sf);
        }
    }
    __syncthreads();

    // ---------- phase A row: partial w ----------
    row_pass(W1s, as_p, &g_wpart[(g * NCHK + c) * DD * PG], lane, warp);

    // ---------- gate A ----------
    __syncthreads();
    __threadfence();
    if (tid == 0) {
        atomicAdd(&g_cntA[g], 1u);
        while (((volatile unsigned*)g_cntA)[g] < NCHK) __nanosleep(20);
    }
    __syncthreads();

    // ---------- phase B: reduce w ; q ; m ----------
    {
        float s = 0.f;
        #pragma unroll
        for (int cc = 0; cc < NCHK; ++cc)
            s += __ldcg(&g_wpart[(g * NCHK + cc) * DD * PG + tid]);
        wp[tid] = s;
    }
    __syncthreads();

    {
        float q0 = 0.f, q1 = 0.f, q2 = 0.f, q3 = 0.f;
        const float4* wp4 = (const float4*)wp;
        #pragma unroll 8
        for (int d = 0; d < DD; ++d) {
            float wv = W1s[d * LD + j];
            float4 wc = wp4[d * 2 + ph];
            q0 += wc.x * wv; q1 += wc.y * wv; q2 += wc.z * wv; q3 += wc.w * wv;
        }
        float qv[4] = {q0, q1, q2, q3};
        #pragma unroll
        for (int k = 0; k < 4; ++k) {
            int p = ph * 4 + k;
            as_p[p * CCHP + j] = asp_p[p * CCHP + j] * qv[k];
        }
    }
    __syncthreads();

    // ---------- phase B row: partial corr ----------
    row_pass(W1s, as_p, &g_cpart[(g * NCHK + c) * DD * PG], lane, warp);

    // ---------- gate B + last-block epilogue ----------
    __syncthreads();
    __threadfence();
    if (tid == 0) {
        unsigned old = atomicAdd(&g_cntB[g], 1u);
        slast = (old == NCHK - 1);
    }
    __syncthreads();
    if (!slast) return;

    {
        float s = 0.f;
        #pragma unroll
        for (int cc = 0; cc < NCHK; ++cc)
            s += __ldcg(&g_cpart[(g * NCHK + cc) * DD * PG + tid]);
        int d = tid >> 3, p = tid & 7;
        csh[p * DD + d] = -s;
    }
    __syncthreads();
    if (warp < PG) {
        int p = warp;
        float c0 = csh[p * DD + lane], c1 = csh[p * DD + 32 + lane];
        float s = c0 * c0 + c1 * c1;
        #pragma unroll
        for (int o = 16; o; o >>= 1) s += __shfl_xor_sync(0xffffffffu, s, o);
        if (lane == 0) red[p] = fminf(sqrtf(s), 0.1f) * 0.1f;
    }
    __syncthreads();
    {
        int p = tid >> 6, m = tid & (DD - 1);
        if (p < nsPerB) {
            float t = (float)(p + 1) * invn1;
            float tfac = t * (1.0f - t);
            float xv = x0g[m] + t * dlt[m];
            out[((p + 1) * B + g) * DD + m] = xv + csh[p * DD + m] * tfac * red[p];
        }
    }
    if (tid == 0) {                      // reset for next graph replay
        g_cntA[g] = 0;
        g_cntB[g] = 0;
        __threadfence();
    }
}

extern "C" void kernel_launch(void* const* d_in, const int* in_sizes, int n_in,
                              void* d_out, int out_size)
{
    const float* x0 = (const float*)d_in[0];
    const float* xT = (const float*)d_in[1];
    const float* W1 = (const float*)d_in[2];
    const float* b1 = (const float*)d_in[3];
    const float* W2 = (const float*)d_in[4];
    float* out = (float*)d_out;

    int H = in_sizes[3];               // 2048
    int Dd = in_sizes[2] / H;          // 64
    int B = in_sizes[0] / Dd;          // 32
    int O = in_sizes[5];               // 64
    int n_steps = out_size / (B * Dd); // 10
    int nInterior = (n_steps - 2) * B; // 256

    if (nInterior <= 0) return;

    size_t smem = (size_t)(DD * LD + CCH + 2 * PG * CCHP + 2 * CCH
                           + 2 * DD * PG + 2 * DD + 16) * sizeof(float);
    static int attr_set = 0;
    if (!attr_set) {
        cudaFuncSetAttribute(geo_one, cudaFuncAttributeMaxDynamicSharedMemorySize, (int)smem);
        attr_set = 1;
    }
    dim3 grid(B, NCHK);
    geo_one<<<grid, NT, smem>>>(x0, xT, W1, b1, W2, out, B, O, n_steps, nInterior);
}